// round 4
// baseline (speedup 1.0000x reference)
#include <cuda_runtime.h>
#include <cstdint>

// TopK per row (B=4096 x D=65536 fp32, k=64), ReLU, scatter into zeros.
// Split into unidirectional memory streams:
//   1) zero_kernel   : pure-write zero fill of out (1 GiB STG stream)
//   2) select_kernel : pure-read top-k per row -> compact (idx,val) buffer
//   3) scatter_kernel: k scattered stores per row (tiny)
// Select hot path: static threshold collect (~407 cand/row expected) + exact
// smem ranking. Exact multi-level histogram fallback for arbitrary inputs
// (tie-break by lowest index, matching jax.lax.top_k).

namespace {

constexpr int TPB   = 512;
constexpr int D_DIM = 65536;
constexpr int NV    = D_DIM / 4;     // 16384 float4 per row
constexpr int CAP   = 2048;          // candidate capacity (smem)
constexpr int SLOT  = 256;           // per-row winner slots in global buffer
constexpr int MAXROWS = 4096;
constexpr float THRESH = 2.5f;       // E[cnt]~407 for N(0,1), >> k=64
constexpr unsigned SMEM_BYTES = (2u * CAP + 4096u) * 4u;  // cand val+idx, hist

__device__ float    g_val[MAXROWS * SLOT];
__device__ unsigned g_idx[MAXROWS * SLOT];

__device__ __forceinline__ unsigned orderKey(float f) {
    unsigned u = __float_as_uint(f);
    return u ^ ((u & 0x80000000u) ? 0xFFFFFFFFu : 0x80000000u);
}
__device__ __forceinline__ float keyToFloat(unsigned key) {
    unsigned u = (key & 0x80000000u) ? (key ^ 0x80000000u) : ~key;
    return __uint_as_float(u);
}

// ---------------------------------------------------------------- zero fill
__global__ void __launch_bounds__(TPB)
zero_kernel(float4* __restrict__ out)
{
    float4* rowp = out + (size_t)blockIdx.x * NV;
    const float4 z = make_float4(0.f, 0.f, 0.f, 0.f);
    #pragma unroll 8
    for (int i = threadIdx.x; i < NV; i += TPB)
        __stcs(&rowp[i], z);
}

// ---------------------------------------------------------------- select
__global__ void __launch_bounds__(TPB)
select_kernel(const float* __restrict__ x, const int* __restrict__ kptr)
{
    extern __shared__ unsigned smem_u[];
    float*    cval = reinterpret_cast<float*>(smem_u);   // [CAP]
    unsigned* cidx = smem_u + CAP;                        // [CAP]
    unsigned* hist = smem_u + 2 * CAP;                    // [4096] fallback
    __shared__ unsigned s_cnt, s_bin, s_rank;
    __shared__ unsigned s_chunk[TPB + 1];                 // fallback scan

    const int tid = threadIdx.x;
    const int row = blockIdx.x;
    const unsigned k = (unsigned)__ldg(kptr);
    const unsigned kw = min(k, (unsigned)SLOT);

    const float4* rowv = reinterpret_cast<const float4*>(x) + (size_t)row * NV;
    float*    gval = g_val + (size_t)row * SLOT;
    unsigned* gidx = g_idx + (size_t)row * SLOT;

    if (tid == 0) s_cnt = 0u;
    __syncthreads();

    // ---- Hot pass: pure read stream + rare candidate collect ----
    #pragma unroll 4
    for (int i = tid; i < NV; i += TPB) {
        float4 v = __ldcs(&rowv[i]);
        float m = fmaxf(fmaxf(v.x, v.y), fmaxf(v.z, v.w));
        if (m >= THRESH) {
            float vv[4] = {v.x, v.y, v.z, v.w};
            #pragma unroll
            for (int l = 0; l < 4; ++l) {
                if (vv[l] >= THRESH) {
                    unsigned p = atomicAdd(&s_cnt, 1u);
                    if (p < CAP) { cval[p] = vv[l]; cidx[p] = (unsigned)(i * 4 + l); }
                }
            }
        }
    }
    __syncthreads();

    const unsigned cnt = s_cnt;
    if (cnt >= k && cnt <= CAP) {
        // exact rank among candidates; rank is unique -> slot position
        for (unsigned j = (unsigned)tid; j < cnt; j += TPB) {
            const float    vj = cval[j];
            const unsigned ij = cidx[j];
            unsigned rank = 0;
            for (unsigned t = 0; t < cnt; ++t) {
                const float vt = cval[t];
                rank += (vt > vj) || (vt == vj && cidx[t] < ij);
            }
            if (rank < kw) { gval[rank] = fmaxf(vj, 0.0f); gidx[rank] = ij; }
        }
        return;
    }

    // ============== Exact fallback: 3-level radix refinement ==============
    // Never runs on the benchmark distribution; correctness for any input.
    const float* rowf = reinterpret_cast<const float*>(rowv);
    unsigned need = k;
    unsigned b0 = 0, b1 = 0, b2 = 0;

    // level 0: bits[31:20]
    for (int i = tid; i < 4096; i += TPB) hist[i] = 0u;
    __syncthreads();
    for (int i = tid; i < D_DIM; i += TPB)
        atomicAdd(&hist[orderKey(rowf[i]) >> 20], 1u);
    __syncthreads();
    if (tid == 0) {
        unsigned acc = 0;
        for (int b = 4095; b >= 0; --b) {
            unsigned c = hist[b];
            if (acc + c >= need) { s_bin = (unsigned)b; s_rank = need - acc; break; }
            acc += c;
        }
    }
    __syncthreads();
    b0 = s_bin; need = s_rank;

    // level 1: bits[19:8] restricted to top bits == b0
    for (int i = tid; i < 4096; i += TPB) hist[i] = 0u;
    __syncthreads();
    for (int i = tid; i < D_DIM; i += TPB) {
        unsigned key = orderKey(rowf[i]);
        if ((key >> 20) == b0) atomicAdd(&hist[(key >> 8) & 0xFFFu], 1u);
    }
    __syncthreads();
    if (tid == 0) {
        unsigned acc = 0;
        for (int b = 4095; b >= 0; --b) {
            unsigned c = hist[b];
            if (acc + c >= need) { s_bin = (unsigned)b; s_rank = need - acc; break; }
            acc += c;
        }
    }
    __syncthreads();
    b1 = s_bin; need = s_rank;

    // level 2: bits[7:0] restricted to top 24 bits
    for (int i = tid; i < 256; i += TPB) hist[i] = 0u;
    __syncthreads();
    const unsigned pre24 = (b0 << 12) | b1;
    for (int i = tid; i < D_DIM; i += TPB) {
        unsigned key = orderKey(rowf[i]);
        if ((key >> 8) == pre24) atomicAdd(&hist[key & 0xFFu], 1u);
    }
    __syncthreads();
    if (tid == 0) {
        unsigned acc = 0;
        for (int b = 255; b >= 0; --b) {
            unsigned c = hist[b];
            if (acc + c >= need) { s_bin = (unsigned)b; s_rank = need - acc; break; }
            acc += c;
        }
        s_cnt = 0u;
    }
    __syncthreads();
    b2 = s_bin; need = s_rank;                    // take `need` of key==pivot
    const unsigned pivot = (pre24 << 8) | b2;

    // winners with key > pivot
    for (int i = tid; i < D_DIM; i += TPB) {
        float v = rowf[i];
        unsigned key = orderKey(v);
        if (key > pivot) {
            unsigned p = atomicAdd(&s_cnt, 1u);
            if (p < kw) { gval[p] = fmaxf(v, 0.0f); gidx[p] = (unsigned)i; }
        }
    }
    __syncthreads();

    // key == pivot: take `need` of them with the SMALLEST indices (jax tie rule).
    // Contiguous chunks per thread -> ordinal = chunk prefix + local ordinal.
    {
        const int CHUNK = D_DIM / TPB;   // 128
        unsigned local = 0;
        for (int i = tid * CHUNK; i < (tid + 1) * CHUNK; ++i)
            local += (orderKey(rowf[i]) == pivot);
        s_chunk[tid + 1] = local;
        if (tid == 0) s_chunk[0] = 0;
        __syncthreads();
        if (tid == 0)
            for (int t = 1; t <= TPB; ++t) s_chunk[t] += s_chunk[t - 1];
        __syncthreads();
        unsigned ord = s_chunk[tid];
        for (int i = tid * CHUNK; i < (tid + 1) * CHUNK; ++i) {
            float v = rowf[i];
            if (orderKey(v) == pivot) {
                if (ord < need) {
                    unsigned p = atomicAdd(&s_cnt, 1u);
                    if (p < kw) { gval[p] = fmaxf(v, 0.0f); gidx[p] = (unsigned)i; }
                }
                ++ord;
            }
        }
    }
}

// ---------------------------------------------------------------- scatter
__global__ void __launch_bounds__(SLOT)
scatter_kernel(const int* __restrict__ kptr, float* __restrict__ out)
{
    const int row = blockIdx.x;
    const unsigned j = threadIdx.x;
    const unsigned k = (unsigned)__ldg(kptr);
    if (j < min(k, (unsigned)SLOT)) {
        unsigned idx = g_idx[(size_t)row * SLOT + j];
        out[(size_t)row * D_DIM + idx] = g_val[(size_t)row * SLOT + j];
    }
}

} // namespace

extern "C" void kernel_launch(void* const* d_in, const int* in_sizes, int n_in,
                              void* d_out, int out_size)
{
    const float* x   = (const float*)d_in[0];
    const int*   kp  = (const int*)d_in[1];
    float*       out = (float*)d_out;

    const int rows = in_sizes[0] / D_DIM;

    cudaFuncSetAttribute(select_kernel,
                         cudaFuncAttributeMaxDynamicSharedMemorySize, SMEM_BYTES);

    zero_kernel<<<rows, TPB>>>(reinterpret_cast<float4*>(out));
    select_kernel<<<rows, TPB, SMEM_BYTES>>>(x, kp);
    scatter_kernel<<<rows, SLOT>>>(kp, out);
}